// round 2
// baseline (speedup 1.0000x reference)
#include <cuda_runtime.h>
#include <math.h>

// Problem constants
#define NB 16384
#define ND 256
#define BM 128
#define BN 128
#define BK 32
#define NT (NB / BN)   // 128 tiles per dimension

// Partial logsumexp state per (row, column-tile) and (col, row-tile).
// 4 * 128 * 16384 * 4B = 33.5 MB of __device__ scratch (allowed; no runtime allocs).
__device__ float g_rowM[(size_t)NT * NB];
__device__ float g_rowS[(size_t)NT * NB];
__device__ float g_colM[(size_t)NT * NB];
__device__ float g_colS[(size_t)NT * NB];
__device__ float g_diag[NB];
__device__ float g_per[NB];

__device__ __forceinline__ unsigned f2tf32(float x) {
    unsigned r;
    asm("cvt.rna.tf32.f32 %0, %1;" : "=r"(r) : "f"(x));
    return r;
}

__device__ __forceinline__ void mma_tf32(float c[4],
                                         unsigned a0, unsigned a1, unsigned a2, unsigned a3,
                                         unsigned b0, unsigned b1) {
    asm volatile(
        "mma.sync.aligned.m16n8k8.row.col.f32.tf32.tf32.f32 "
        "{%0,%1,%2,%3}, {%4,%5,%6,%7}, {%8,%9}, {%0,%1,%2,%3};\n"
        : "+f"(c[0]), "+f"(c[1]), "+f"(c[2]), "+f"(c[3])
        : "r"(a0), "r"(a1), "r"(a2), "r"(a3), "r"(b0), "r"(b1));
}

// One CTA = one 128x128 logits tile. TF32 tensor-core GEMM + fused
// row/col partial-logsumexp epilogue. No atomics (deterministic).
__global__ __launch_bounds__(256) void clip_gemm(const float* __restrict__ Ag,
                                                 const float* __restrict__ Bg,
                                                 const float* __restrict__ d_ls) {
    // SMEM: [m][k] layout, stride 36 words -> conflict-free fragment loads
    __shared__ unsigned As[BM][BK + 4];
    __shared__ unsigned Bs[BN][BK + 4];
    __shared__ float redM[BM][4];
    __shared__ float redS[BM][4];

    const int tN = blockIdx.x, tM = blockIdx.y;
    const int tid = threadIdx.x;
    const int warp = tid >> 5, lane = tid & 31;
    const int wm = warp >> 2, wn = warp & 3;   // 2 x 4 warp grid; warp tile 64x32
    const int g = lane >> 2, t = lane & 3;     // mma group / thread-in-group

    const float* Aptr = Ag + (size_t)tM * BM * ND;
    const float* Bptr = Bg + (size_t)tN * BN * ND;

    const int ldRow = tid >> 3;        // 0..31
    const int ldK4  = (tid & 7) * 4;   // 0,4,...,28

    float acc[4][4][4];
#pragma unroll
    for (int i = 0; i < 4; i++)
#pragma unroll
        for (int j = 0; j < 4; j++)
#pragma unroll
            for (int k = 0; k < 4; k++) acc[i][j][k] = 0.f;

    // Prefetch k-chunk 0
    float4 stA[4], stB[4];
#pragma unroll
    for (int r = 0; r < 4; r++) {
        stA[r] = *(const float4*)(Aptr + (size_t)(ldRow + 32 * r) * ND + ldK4);
        stB[r] = *(const float4*)(Bptr + (size_t)(ldRow + 32 * r) * ND + ldK4);
    }

    for (int kc = 0; kc < ND / BK; kc++) {
        __syncthreads();   // previous chunk's compute done before SMEM overwrite
#pragma unroll
        for (int r = 0; r < 4; r++) {
            int row = ldRow + 32 * r;
            uint4 ua = make_uint4(f2tf32(stA[r].x), f2tf32(stA[r].y),
                                  f2tf32(stA[r].z), f2tf32(stA[r].w));
            *(uint4*)&As[row][ldK4] = ua;
            uint4 ub = make_uint4(f2tf32(stB[r].x), f2tf32(stB[r].y),
                                  f2tf32(stB[r].z), f2tf32(stB[r].w));
            *(uint4*)&Bs[row][ldK4] = ub;
        }
        __syncthreads();
        if (kc + 1 < ND / BK) {   // prefetch next chunk under compute
            const float* Ap2 = Aptr + (kc + 1) * BK;
            const float* Bp2 = Bptr + (kc + 1) * BK;
#pragma unroll
            for (int r = 0; r < 4; r++) {
                stA[r] = *(const float4*)(Ap2 + (size_t)(ldRow + 32 * r) * ND + ldK4);
                stB[r] = *(const float4*)(Bp2 + (size_t)(ldRow + 32 * r) * ND + ldK4);
            }
        }
#pragma unroll
        for (int ks = 0; ks < 4; ks++) {
            const int kk = ks * 8;
            unsigned a[4][4], b[4][2];
#pragma unroll
            for (int mt = 0; mt < 4; mt++) {
                int m0 = wm * 64 + mt * 16;
                a[mt][0] = As[m0 + g][kk + t];
                a[mt][1] = As[m0 + g + 8][kk + t];
                a[mt][2] = As[m0 + g][kk + t + 4];
                a[mt][3] = As[m0 + g + 8][kk + t + 4];
            }
#pragma unroll
            for (int nt = 0; nt < 4; nt++) {
                int n0 = wn * 32 + nt * 8;
                b[nt][0] = Bs[n0 + g][kk + t];
                b[nt][1] = Bs[n0 + g][kk + t + 4];
            }
#pragma unroll
            for (int mt = 0; mt < 4; mt++)
#pragma unroll
                for (int nt = 0; nt < 4; nt++)
                    mma_tf32(acc[mt][nt], a[mt][0], a[mt][1], a[mt][2], a[mt][3],
                             b[nt][0], b[nt][1]);
        }
    }

    // ---- epilogue ----
    const float scale = fminf(expf(__ldg(d_ls)), 100.0f);
#pragma unroll
    for (int mt = 0; mt < 4; mt++)
#pragma unroll
        for (int nt = 0; nt < 4; nt++)
#pragma unroll
            for (int j = 0; j < 4; j++) acc[mt][nt][j] *= scale;

    // accum reg j -> local row = wm*64 + mt*16 + g + 8*(j>>1),
    //                local col = wn*32 + nt*8 + 2*t + (j&1)

    // Diagonal
    if (tM == tN) {
#pragma unroll
        for (int mt = 0; mt < 4; mt++)
#pragma unroll
            for (int nt = 0; nt < 4; nt++)
#pragma unroll
                for (int j = 0; j < 4; j++) {
                    int r = wm * 64 + mt * 16 + g + 8 * (j >> 1);
                    int c = wn * 32 + nt * 8 + 2 * t + (j & 1);
                    if (r == c) g_diag[tM * BM + r] = acc[mt][nt][j];
                }
    }

    // ---- row partials: per-warp max over 32 cols, combine 4 n-warps via SMEM ----
    float rm[4][2], rs[4][2];
#pragma unroll
    for (int mt = 0; mt < 4; mt++)
#pragma unroll
        for (int p = 0; p < 2; p++) {
            float m = -3.4e38f;
#pragma unroll
            for (int nt = 0; nt < 4; nt++)
                m = fmaxf(m, fmaxf(acc[mt][nt][2 * p], acc[mt][nt][2 * p + 1]));
            m = fmaxf(m, __shfl_xor_sync(0xffffffffu, m, 1));
            m = fmaxf(m, __shfl_xor_sync(0xffffffffu, m, 2));
            rm[mt][p] = m;
        }
    if (t == 0) {
#pragma unroll
        for (int mt = 0; mt < 4; mt++)
#pragma unroll
            for (int p = 0; p < 2; p++)
                redM[wm * 64 + mt * 16 + g + 8 * p][wn] = rm[mt][p];
    }
    __syncthreads();
#pragma unroll
    for (int mt = 0; mt < 4; mt++)
#pragma unroll
        for (int p = 0; p < 2; p++) {
            int r = wm * 64 + mt * 16 + g + 8 * p;
            float m = fmaxf(fmaxf(redM[r][0], redM[r][1]), fmaxf(redM[r][2], redM[r][3]));
            rm[mt][p] = m;
            float s = 0.f;
#pragma unroll
            for (int nt = 0; nt < 4; nt++)
                s += __expf(acc[mt][nt][2 * p] - m) + __expf(acc[mt][nt][2 * p + 1] - m);
            s += __shfl_xor_sync(0xffffffffu, s, 1);
            s += __shfl_xor_sync(0xffffffffu, s, 2);
            rs[mt][p] = s;
        }
    if (t == 0) {
#pragma unroll
        for (int mt = 0; mt < 4; mt++)
#pragma unroll
            for (int p = 0; p < 2; p++)
                redS[wm * 64 + mt * 16 + g + 8 * p][wn] = rs[mt][p];
    }
    __syncthreads();
    if (wn == 0 && t == 0) {
#pragma unroll
        for (int mt = 0; mt < 4; mt++)
#pragma unroll
            for (int p = 0; p < 2; p++) {
                int r = wm * 64 + mt * 16 + g + 8 * p;
                float s = redS[r][0] + redS[r][1] + redS[r][2] + redS[r][3];
                int rg = tM * BM + r;
                g_rowM[(size_t)tN * NB + rg] = rm[mt][p];
                g_rowS[(size_t)tN * NB + rg] = s;
            }
    }
    __syncthreads();   // everyone past redS reads before col phase reuses arrays

    // ---- col partials: per-warp max over 64 rows, combine 2 m-warps ----
    float cm[4][2], cs[4][2];
#pragma unroll
    for (int nt = 0; nt < 4; nt++)
#pragma unroll
        for (int q = 0; q < 2; q++) {
            float m = -3.4e38f;
#pragma unroll
            for (int mt = 0; mt < 4; mt++)
                m = fmaxf(m, fmaxf(acc[mt][nt][q], acc[mt][nt][2 + q]));
            m = fmaxf(m, __shfl_xor_sync(0xffffffffu, m, 4));
            m = fmaxf(m, __shfl_xor_sync(0xffffffffu, m, 8));
            m = fmaxf(m, __shfl_xor_sync(0xffffffffu, m, 16));
            cm[nt][q] = m;
        }
    if (g == 0) {
#pragma unroll
        for (int nt = 0; nt < 4; nt++)
#pragma unroll
            for (int q = 0; q < 2; q++)
                redM[wn * 32 + nt * 8 + 2 * t + q][wm] = cm[nt][q];
    }
    __syncthreads();
#pragma unroll
    for (int nt = 0; nt < 4; nt++)
#pragma unroll
        for (int q = 0; q < 2; q++) {
            int c = wn * 32 + nt * 8 + 2 * t + q;
            float m = fmaxf(redM[c][0], redM[c][1]);
            cm[nt][q] = m;
            float s = 0.f;
#pragma unroll
            for (int mt = 0; mt < 4; mt++)
                s += __expf(acc[mt][nt][q] - m) + __expf(acc[mt][nt][2 + q] - m);
            s += __shfl_xor_sync(0xffffffffu, s, 4);
            s += __shfl_xor_sync(0xffffffffu, s, 8);
            s += __shfl_xor_sync(0xffffffffu, s, 16);
            cs[nt][q] = s;
        }
    if (g == 0) {
#pragma unroll
        for (int nt = 0; nt < 4; nt++)
#pragma unroll
            for (int q = 0; q < 2; q++)
                redS[wn * 32 + nt * 8 + 2 * t + q][wm] = cs[nt][q];
    }
    __syncthreads();
    if (wm == 0 && g == 0) {
#pragma unroll
        for (int nt = 0; nt < 4; nt++)
#pragma unroll
            for (int q = 0; q < 2; q++) {
                int c = wn * 32 + nt * 8 + 2 * t + q;
                float s = redS[c][0] + redS[c][1];
                int cg = tN * BN + c;
                g_colM[(size_t)tM * NB + cg] = cm[nt][q];
                g_colS[(size_t)tM * NB + cg] = s;
            }
    }
}

// Merge 128 tile-partials per row / per col into final LSEs.
__global__ void clip_merge() {
    int i = blockIdx.x * blockDim.x + threadIdx.x;
    if (i >= NB) return;

    float m = -3.4e38f;
    for (int tt = 0; tt < NT; tt++) m = fmaxf(m, g_rowM[(size_t)tt * NB + i]);
    float s = 0.f;
    for (int tt = 0; tt < NT; tt++)
        s += g_rowS[(size_t)tt * NB + i] * __expf(g_rowM[(size_t)tt * NB + i] - m);
    float lr = m + __logf(s);

    float m2 = -3.4e38f;
    for (int tt = 0; tt < NT; tt++) m2 = fmaxf(m2, g_colM[(size_t)tt * NB + i]);
    float s2 = 0.f;
    for (int tt = 0; tt < NT; tt++)
        s2 += g_colS[(size_t)tt * NB + i] * __expf(g_colM[(size_t)tt * NB + i] - m2);
    float lc = m2 + __logf(s2);

    g_per[i] = lr + lc - 2.0f * g_diag[i];
}

// Deterministic fixed-order final mean.
__global__ void clip_reduce(float* out, int out_size) {
    __shared__ float sm[1024];
    int tid = threadIdx.x;
    float s = 0.f;
    for (int i = tid; i < NB; i += 1024) s += g_per[i];
    sm[tid] = s;
    __syncthreads();
    for (int off = 512; off > 0; off >>= 1) {
        if (tid < off) sm[tid] += sm[tid + off];
        __syncthreads();
    }
    float loss = sm[0] / (2.0f * NB);
    for (int i = tid; i < out_size; i += 1024) out[i] = loss;
}

extern "C" void kernel_launch(void* const* d_in, const int* in_sizes, int n_in,
                              void* d_out, int out_size) {
    const float* z_schema = (const float*)d_in[0];
    const float* z_seal   = (const float*)d_in[1];
    const float* ls       = (const float*)d_in[2];
    (void)in_sizes; (void)n_in;

    dim3 grid(NT, NT);
    clip_gemm<<<grid, 256>>>(z_schema, z_seal, ls);
    clip_merge<<<NB / 256, 256>>>();
    clip_reduce<<<1, 1024>>>((float*)d_out, out_size);
}

// round 3
// speedup vs baseline: 2.0981x; 2.0981x over previous
#include <cuda_runtime.h>
#include <cuda_bf16.h>
#include <math.h>

// Problem constants
#define NB 16384
#define ND 256
#define BM 128
#define BN 128
#define BKc 64            // bf16 k-elements per SMEM chunk (128 bytes/row)
#define NCH (ND / BKc)    // 4 chunks
#define NT (NB / BN)      // 128 tiles per dimension

// Partial logsumexp state per (row, column-tile) and (col, row-tile).
__device__ float g_rowM[(size_t)NT * NB];
__device__ float g_rowS[(size_t)NT * NB];
__device__ float g_colM[(size_t)NT * NB];
__device__ float g_colS[(size_t)NT * NB];
__device__ float g_diag[NB];
__device__ float g_per[NB];
// bf16 pre-converted operands
__device__ __align__(16) __nv_bfloat16 g_Abf[(size_t)NB * ND];
__device__ __align__(16) __nv_bfloat16 g_Bbf[(size_t)NB * ND];

// fp32 -> bf16 conversion pass (vectorized, ~50 MB of traffic total)
__global__ void clip_convert(const float* __restrict__ A, const float* __restrict__ B) {
    int i = blockIdx.x * blockDim.x + threadIdx.x;   // handles 4 elems of each matrix
    float4 a = ((const float4*)A)[i];
    __nv_bfloat162 lo = __floats2bfloat162_rn(a.x, a.y);
    __nv_bfloat162 hi = __floats2bfloat162_rn(a.z, a.w);
    ((uint2*)g_Abf)[i] = make_uint2(*(unsigned*)&lo, *(unsigned*)&hi);
    float4 b = ((const float4*)B)[i];
    lo = __floats2bfloat162_rn(b.x, b.y);
    hi = __floats2bfloat162_rn(b.z, b.w);
    ((uint2*)g_Bbf)[i] = make_uint2(*(unsigned*)&lo, *(unsigned*)&hi);
}

__device__ __forceinline__ void mma_bf16(float c[4], const unsigned a[4],
                                         unsigned b0, unsigned b1) {
    asm volatile(
        "mma.sync.aligned.m16n8k16.row.col.f32.bf16.bf16.f32 "
        "{%0,%1,%2,%3}, {%4,%5,%6,%7}, {%8,%9}, {%0,%1,%2,%3};\n"
        : "+f"(c[0]), "+f"(c[1]), "+f"(c[2]), "+f"(c[3])
        : "r"(a[0]), "r"(a[1]), "r"(a[2]), "r"(a[3]), "r"(b0), "r"(b1));
}

// One CTA = one 128x128 logits tile. bf16 tensor cores, ldmatrix fragment
// loads, cp.async double-buffered SMEM pipeline, fused LSE-partial epilogue.
__global__ __launch_bounds__(256, 2) void clip_gemm(const float* __restrict__ d_ls) {
    extern __shared__ char dyns[];   // 2 bufs x (A 16KB + B 16KB) = 64KB
    const unsigned sBase = (unsigned)__cvta_generic_to_shared(dyns);

    __shared__ float redM[BM][4];
    __shared__ float redS[BM][4];

    const int tN = blockIdx.x, tM = blockIdx.y;
    const int tid = threadIdx.x;
    const int warp = tid >> 5, lane = tid & 31;
    const int wm = warp >> 2, wn = warp & 3;   // 2 x 4 warps; warp tile 64x32
    const int g = lane >> 2, t = lane & 3;

    // cp.async load mapping: 16B segments, 8 per 128B row
    const int seg = tid & 7;
    const int row0 = tid >> 3;   // 0..31

    const __nv_bfloat16* Ag = g_Abf + (size_t)tM * BM * ND;
    const __nv_bfloat16* Bg = g_Bbf + (size_t)tN * BN * ND;

    // ldmatrix per-thread address components (row part fixed for whole kernel)
    unsigned aRow[4], swA[4];
#pragma unroll
    for (int mt = 0; mt < 4; mt++) {
        int r = wm * 64 + mt * 16 + (lane & 15);
        aRow[mt] = r * 128;
        swA[mt] = (r & 7) << 4;
    }
    const unsigned clA = (unsigned)((lane >> 4) << 4);       // 0 or 16 bytes (k halves)
    unsigned bRow[2], swB[2];
#pragma unroll
    for (int p = 0; p < 2; p++) {
        int r = wn * 32 + p * 16 + (lane & 7) + ((lane >> 4) << 3);
        bRow[p] = r * 128;
        swB[p] = (r & 7) << 4;
    }
    const unsigned clB = (unsigned)(((lane >> 3) & 1) << 4);

    float acc[4][4][4];
#pragma unroll
    for (int i = 0; i < 4; i++)
#pragma unroll
        for (int j = 0; j < 4; j++)
#pragma unroll
            for (int k = 0; k < 4; k++) acc[i][j][k] = 0.f;

    auto load_chunk = [&](int kc, int buf) {
        unsigned aB = sBase + buf * 32768;
        unsigned bB = aB + 16384;
#pragma unroll
        for (int i = 0; i < 4; i++) {
            int r = row0 + 32 * i;
            unsigned soff = (unsigned)(r * 128) + ((unsigned)(seg ^ (r & 7)) << 4);
            const __nv_bfloat16* srcA = Ag + (size_t)r * ND + kc * BKc + seg * 8;
            asm volatile("cp.async.cg.shared.global [%0], [%1], 16;\n"
                         :: "r"(aB + soff), "l"(__cvta_generic_to_global(srcA)));
            const __nv_bfloat16* srcB = Bg + (size_t)r * ND + kc * BKc + seg * 8;
            asm volatile("cp.async.cg.shared.global [%0], [%1], 16;\n"
                         :: "r"(bB + soff), "l"(__cvta_generic_to_global(srcB)));
        }
        asm volatile("cp.async.commit_group;\n");
    };

    auto compute = [&](int buf) {
        unsigned aB = sBase + buf * 32768;
        unsigned bB = aB + 16384;
#pragma unroll
        for (int ks = 0; ks < 4; ks++) {
            const unsigned k2 = (unsigned)(ks * 32);   // byte offset of k0 within row
            unsigned a[4][4], b[2][4];
#pragma unroll
            for (int mt = 0; mt < 4; mt++) {
                unsigned addr = aB + aRow[mt] + ((k2 + clA) ^ swA[mt]);
                asm volatile(
                    "ldmatrix.sync.aligned.m8n8.x4.shared.b16 {%0,%1,%2,%3}, [%4];\n"
                    : "=r"(a[mt][0]), "=r"(a[mt][1]), "=r"(a[mt][2]), "=r"(a[mt][3])
                    : "r"(addr));
            }
#pragma unroll
            for (int p = 0; p < 2; p++) {
                unsigned addr = bB + bRow[p] + ((k2 + clB) ^ swB[p]);
                asm volatile(
                    "ldmatrix.sync.aligned.m8n8.x4.shared.b16 {%0,%1,%2,%3}, [%4];\n"
                    : "=r"(b[p][0]), "=r"(b[p][1]), "=r"(b[p][2]), "=r"(b[p][3])
                    : "r"(addr));
            }
#pragma unroll
            for (int mt = 0; mt < 4; mt++)
#pragma unroll
                for (int nt = 0; nt < 4; nt++)
                    mma_bf16(acc[mt][nt], a[mt],
                             b[nt >> 1][(nt & 1) * 2], b[nt >> 1][(nt & 1) * 2 + 1]);
        }
    };

    // ---- pipelined mainloop ----
    load_chunk(0, 0);
    load_chunk(1, 1);
#pragma unroll
    for (int kc = 0; kc < NCH; kc++) {
        if (kc < NCH - 1) asm volatile("cp.async.wait_group 1;\n");
        else              asm volatile("cp.async.wait_group 0;\n");
        __syncthreads();
        compute(kc & 1);
        if (kc + 2 < NCH) {
            __syncthreads();            // all warps done with this buffer
            load_chunk(kc + 2, kc & 1);
        }
    }

    // ---- epilogue (fragment layout identical to m16n8k8: reg j ->
    //      row = wm*64+mt*16+g+8*(j>>1), col = wn*32+nt*8+2*t+(j&1)) ----
    const float scale = fminf(expf(__ldg(d_ls)), 100.0f);
#pragma unroll
    for (int mt = 0; mt < 4; mt++)
#pragma unroll
        for (int nt = 0; nt < 4; nt++)
#pragma unroll
            for (int j = 0; j < 4; j++) acc[mt][nt][j] *= scale;

    // Diagonal
    if (tM == tN) {
#pragma unroll
        for (int mt = 0; mt < 4; mt++)
#pragma unroll
            for (int nt = 0; nt < 4; nt++)
#pragma unroll
                for (int j = 0; j < 4; j++) {
                    int r = wm * 64 + mt * 16 + g + 8 * (j >> 1);
                    int c = wn * 32 + nt * 8 + 2 * t + (j & 1);
                    if (r == c) g_diag[tM * BM + r] = acc[mt][nt][j];
                }
    }

    // ---- row partials ----
    float rm[4][2], rs[4][2];
#pragma unroll
    for (int mt = 0; mt < 4; mt++)
#pragma unroll
        for (int p = 0; p < 2; p++) {
            float m = -3.4e38f;
#pragma unroll
            for (int nt = 0; nt < 4; nt++)
                m = fmaxf(m, fmaxf(acc[mt][nt][2 * p], acc[mt][nt][2 * p + 1]));
            m = fmaxf(m, __shfl_xor_sync(0xffffffffu, m, 1));
            m = fmaxf(m, __shfl_xor_sync(0xffffffffu, m, 2));
            rm[mt][p] = m;
        }
    if (t == 0) {
#pragma unroll
        for (int mt = 0; mt < 4; mt++)
#pragma unroll
            for (int p = 0; p < 2; p++)
                redM[wm * 64 + mt * 16 + g + 8 * p][wn] = rm[mt][p];
    }
    __syncthreads();
#pragma unroll
    for (int mt = 0; mt < 4; mt++)
#pragma unroll
        for (int p = 0; p < 2; p++) {
            int r = wm * 64 + mt * 16 + g + 8 * p;
            float m = fmaxf(fmaxf(redM[r][0], redM[r][1]), fmaxf(redM[r][2], redM[r][3]));
            rm[mt][p] = m;
            float s = 0.f;
#pragma unroll
            for (int nt = 0; nt < 4; nt++)
                s += __expf(acc[mt][nt][2 * p] - m) + __expf(acc[mt][nt][2 * p + 1] - m);
            s += __shfl_xor_sync(0xffffffffu, s, 1);
            s += __shfl_xor_sync(0xffffffffu, s, 2);
            rs[mt][p] = s;
        }
    if (t == 0) {
#pragma unroll
        for (int mt = 0; mt < 4; mt++)
#pragma unroll
            for (int p = 0; p < 2; p++)
                redS[wm * 64 + mt * 16 + g + 8 * p][wn] = rs[mt][p];
    }
    __syncthreads();
    if (wn == 0 && t == 0) {
#pragma unroll
        for (int mt = 0; mt < 4; mt++)
#pragma unroll
            for (int p = 0; p < 2; p++) {
                int r = wm * 64 + mt * 16 + g + 8 * p;
                float s = redS[r][0] + redS[r][1] + redS[r][2] + redS[r][3];
                int rg = tM * BM + r;
                g_rowM[(size_t)tN * NB + rg] = rm[mt][p];
                g_rowS[(size_t)tN * NB + rg] = s;
            }
    }
    __syncthreads();

    // ---- col partials ----
    float cm[4][2], cs[4][2];
#pragma unroll
    for (int nt = 0; nt < 4; nt++)
#pragma unroll
        for (int q = 0; q < 2; q++) {
            float m = -3.4e38f;
#pragma unroll
            for (int mt = 0; mt < 4; mt++)
                m = fmaxf(m, fmaxf(acc[mt][nt][q], acc[mt][nt][2 + q]));
            m = fmaxf(m, __shfl_xor_sync(0xffffffffu, m, 4));
            m = fmaxf(m, __shfl_xor_sync(0xffffffffu, m, 8));
            m = fmaxf(m, __shfl_xor_sync(0xffffffffu, m, 16));
            cm[nt][q] = m;
        }
    if (g == 0) {
#pragma unroll
        for (int nt = 0; nt < 4; nt++)
#pragma unroll
            for (int q = 0; q < 2; q++)
                redM[wn * 32 + nt * 8 + 2 * t + q][wm] = cm[nt][q];
    }
    __syncthreads();
#pragma unroll
    for (int nt = 0; nt < 4; nt++)
#pragma unroll
        for (int q = 0; q < 2; q++) {
            int c = wn * 32 + nt * 8 + 2 * t + q;
            float m = fmaxf(redM[c][0], redM[c][1]);
            cm[nt][q] = m;
            float s = 0.f;
#pragma unroll
            for (int mt = 0; mt < 4; mt++)
                s += __expf(acc[mt][nt][q] - m) + __expf(acc[mt][nt][2 + q] - m);
            s += __shfl_xor_sync(0xffffffffu, s, 4);
            s += __shfl_xor_sync(0xffffffffu, s, 8);
            s += __shfl_xor_sync(0xffffffffu, s, 16);
            cs[nt][q] = s;
        }
    if (g == 0) {
#pragma unroll
        for (int nt = 0; nt < 4; nt++)
#pragma unroll
            for (int q = 0; q < 2; q++)
                redS[wn * 32 + nt * 8 + 2 * t + q][wm] = cs[nt][q];
    }
    __syncthreads();
    if (wm == 0 && g == 0) {
#pragma unroll
        for (int nt = 0; nt < 4; nt++)
#pragma unroll
            for (int q = 0; q < 2; q++) {
                int c = wn * 32 + nt * 8 + 2 * t + q;
                float s = redS[c][0] + redS[c][1];
                int cg = tN * BN + c;
                g_colM[(size_t)tM * NB + cg] = cm[nt][q];
                g_colS[(size_t)tM * NB + cg] = s;
            }
    }
}

// Merge 128 tile-partials per row / per col into final LSEs.
__global__ void clip_merge() {
    int i = blockIdx.x * blockDim.x + threadIdx.x;
    if (i >= NB) return;

    float m = -3.4e38f;
    for (int tt = 0; tt < NT; tt++) m = fmaxf(m, g_rowM[(size_t)tt * NB + i]);
    float s = 0.f;
    for (int tt = 0; tt < NT; tt++)
        s += g_rowS[(size_t)tt * NB + i] * __expf(g_rowM[(size_t)tt * NB + i] - m);
    float lr = m + __logf(s);

    float m2 = -3.4e38f;
    for (int tt = 0; tt < NT; tt++) m2 = fmaxf(m2, g_colM[(size_t)tt * NB + i]);
    float s2 = 0.f;
    for (int tt = 0; tt < NT; tt++)
        s2 += g_colS[(size_t)tt * NB + i] * __expf(g_colM[(size_t)tt * NB + i] - m2);
    float lc = m2 + __logf(s2);

    g_per[i] = lr + lc - 2.0f * g_diag[i];
}

// Deterministic fixed-order final mean.
__global__ void clip_reduce(float* out, int out_size) {
    __shared__ float sm[1024];
    int tid = threadIdx.x;
    float s = 0.f;
    for (int i = tid; i < NB; i += 1024) s += g_per[i];
    sm[tid] = s;
    __syncthreads();
    for (int off = 512; off > 0; off >>= 1) {
        if (tid < off) sm[tid] += sm[tid + off];
        __syncthreads();
    }
    float loss = sm[0] / (2.0f * NB);
    for (int i = tid; i < out_size; i += 1024) out[i] = loss;
}

extern "C" void kernel_launch(void* const* d_in, const int* in_sizes, int n_in,
                              void* d_out, int out_size) {
    const float* z_schema = (const float*)d_in[0];
    const float* z_seal   = (const float*)d_in[1];
    const float* ls       = (const float*)d_in[2];
    (void)in_sizes; (void)n_in;

    static bool attr_set = false;
    if (!attr_set) {
        cudaFuncSetAttribute(clip_gemm, cudaFuncAttributeMaxDynamicSharedMemorySize, 65536);
        attr_set = true;
    }

    clip_convert<<<(NB * ND / 4) / 256, 256>>>(z_schema, z_seal);
    dim3 grid(NT, NT);
    clip_gemm<<<grid, 256, 65536>>>(ls);
    clip_merge<<<NB / 256, 256>>>();
    clip_reduce<<<1, 1024>>>((float*)d_out, out_size);
}